// round 14
// baseline (speedup 1.0000x reference)
#include <cuda_runtime.h>
#include <cuda_fp16.h>
#include <math.h>
#include <stdint.h>

#define D_MODEL 1024
#define NHEAD   16
#define DKH     64
#define BATCH   4
#define SEQ     2048
#define M_TOT   (BATCH*SEQ)     // 8192
#define BH      (BATCH*NHEAD)   // 64

// ---- scratch (__device__ globals: allocation-free rule) ----
__device__ __half g_x1[(size_t)M_TOT*D_MODEL];       // x single fp16
__device__ __half g_a1[(size_t)M_TOT*D_MODEL];       // attn out single fp16
__device__ __half g_wh[4][(size_t)D_MODEL*D_MODEL];  // weights single fp16
// q (pre-scaled 1/8), k, v — all single fp16 [B,H,S,dk]
__device__ __half g_q1[(size_t)BH*SEQ*DKH];
__device__ __half g_k1[(size_t)BH*SEQ*DKH];
__device__ __half g_v1[(size_t)BH*SEQ*DKH];

typedef unsigned long long ull;

__device__ __forceinline__ uint32_t smem_u32(const void* p) {
    uint32_t a;
    asm("{ .reg .u64 t; cvta.to.shared.u64 t, %1; cvt.u32.u64 %0, t; }" : "=r"(a) : "l"(p));
    return a;
}
__device__ __forceinline__ void ldsm4(uint32_t& r0, uint32_t& r1, uint32_t& r2, uint32_t& r3,
                                      uint32_t addr) {
    asm volatile("ldmatrix.sync.aligned.m8n8.x4.shared.b16 {%0,%1,%2,%3}, [%4];"
                 : "=r"(r0), "=r"(r1), "=r"(r2), "=r"(r3) : "r"(addr));
}
__device__ __forceinline__ void ldsm4t(uint32_t& r0, uint32_t& r1, uint32_t& r2, uint32_t& r3,
                                       uint32_t addr) {
    asm volatile("ldmatrix.sync.aligned.m8n8.x4.trans.shared.b16 {%0,%1,%2,%3}, [%4];"
                 : "=r"(r0), "=r"(r1), "=r"(r2), "=r"(r3) : "r"(addr));
}
__device__ __forceinline__ void mma16816(float* c, const uint32_t* a, const uint32_t* b) {
    asm volatile(
        "mma.sync.aligned.m16n8k16.row.col.f32.f16.f16.f32 "
        "{%0,%1,%2,%3}, {%4,%5,%6,%7}, {%8,%9}, {%0,%1,%2,%3};"
        : "+f"(c[0]), "+f"(c[1]), "+f"(c[2]), "+f"(c[3])
        : "r"(a[0]), "r"(a[1]), "r"(a[2]), "r"(a[3]), "r"(b[0]), "r"(b[1]));
}
// pack two f32 -> fp16x2 (e0 low)
__device__ __forceinline__ uint32_t packh2(float e0, float e1) {
    __half2 hh = __floats2half2_rn(e0, e1);
    return *reinterpret_cast<uint32_t*>(&hh);
}

// ============================================================================
// conversions: x -> g_x1;  4 weights -> g_wh (single launch, blockIdx.y)
// ============================================================================
__global__ void conv_x_kernel(const float* __restrict__ in, int n4)
{
    int i = blockIdx.x * blockDim.x + threadIdx.x;
    if (i >= n4) return;
    float4 v = reinterpret_cast<const float4*>(in)[i];
    __half h[4];
    h[0] = __float2half_rn(v.x); h[1] = __float2half_rn(v.y);
    h[2] = __float2half_rn(v.z); h[3] = __float2half_rn(v.w);
    reinterpret_cast<ull*>(g_x1)[i] = *reinterpret_cast<ull*>(h);
}

__global__ void conv_w4_kernel(const float* __restrict__ W0, const float* __restrict__ W1,
                               const float* __restrict__ W2, const float* __restrict__ W3,
                               int n4)
{
    int which = blockIdx.y;
    const float* src = (which == 0) ? W0 : (which == 1) ? W1 : (which == 2) ? W2 : W3;
    int i = blockIdx.x * blockDim.x + threadIdx.x;
    if (i >= n4) return;
    float4 v = reinterpret_cast<const float4*>(src)[i];
    __half h[4];
    h[0] = __float2half_rn(v.x); h[1] = __float2half_rn(v.y);
    h[2] = __float2half_rn(v.z); h[3] = __float2half_rn(v.w);
    reinterpret_cast<ull*>(g_wh[which])[i] = *reinterpret_cast<ull*>(h);
}

// ============================================================================
// mma.sync fp16 GEMM — single-pass, CTA tile 256x128, K-chunk 64.
// 512 threads, warp grid 4(m)x4(n), warp tile 64x32 (16 MMAs/k-step).
// 2-stage ring, load(c+1) issued right after the barrier (overlaps compute c).
// Epilogues: 0 q/8, 1 K, 2 V (fp16); 3 fp32+bias.
// ============================================================================
#define ATILE_B 32768                // 256 rows x 128B
#define BTILE_B 16384                // 128 rows x 128B
#define GSTAGE_B (ATILE_B + BTILE_B) // 49152
#define GEMM_SMEM (2 * GSTAGE_B)     // 98304

__device__ __forceinline__ void load_chunk(
    uint32_t sstage, const __half* A, const __half* B,
    int m0, int n0, int k0, int tid)
{
    // A: 256 rows x 8 x 16B = 2048 vecs -> 4 per thread
    #pragma unroll
    for (int i = 0; i < 4; ++i) {
        int idx = tid + i * 512;
        int row = idx >> 3, c = idx & 7;
        const void* g = A + (size_t)(m0 + row) * D_MODEL + k0 + c * 8;
        uint32_t s = sstage + row * 128 + ((c ^ (row & 7)) * 16);
        asm volatile("cp.async.cg.shared.global [%0], [%1], 16;" :: "r"(s), "l"(g));
    }
    // B: 128 rows x 8 x 16B = 1024 vecs -> 2 per thread
    #pragma unroll
    for (int i = 0; i < 2; ++i) {
        int idx = tid + i * 512;
        int row = idx >> 3, c = idx & 7;
        const void* g = B + (size_t)(n0 + row) * D_MODEL + k0 + c * 8;
        uint32_t s = sstage + ATILE_B + row * 128 + ((c ^ (row & 7)) * 16);
        asm volatile("cp.async.cg.shared.global [%0], [%1], 16;" :: "r"(s), "l"(g));
    }
}

__global__ __launch_bounds__(512, 1)
void gemm_mma_kernel(int mode_base, const float* __restrict__ b0,
                     const float* __restrict__ b1, const float* __restrict__ b2,
                     float* __restrict__ outp)
{
    extern __shared__ __align__(128) char smem[];
    const uint32_t sb = smem_u32(smem);

    const int mode = (mode_base == 3) ? 3 : (int)blockIdx.z;
    const float* bias = (mode == 1) ? b1 : (mode == 2) ? b2 : b0;
    const __half* A = (mode == 3) ? g_a1 : g_x1;
    const __half* B = g_wh[mode];

    const int tid = threadIdx.x, wid = tid >> 5, lane = tid & 31;
    const int m0 = blockIdx.y * 256, n0 = blockIdx.x * 128;
    const int mw = (wid & 3) * 64, nw = (wid >> 2) * 32;   // warp tile 64x32
    const int mid = lane >> 3, lrow = lane & 7;

    float acc[4][4][4];
    #pragma unroll
    for (int im = 0; im < 4; ++im)
        #pragma unroll
        for (int jn = 0; jn < 4; ++jn)
            #pragma unroll
            for (int r = 0; r < 4; ++r) acc[im][jn][r] = 0.f;

    load_chunk(sb, A, B, m0, n0, 0, tid);
    asm volatile("cp.async.commit_group;" ::: "memory");

    const int NCH = D_MODEL / 64;   // 16
    for (int c = 0; c < NCH; ++c) {
        const uint32_t sstage = sb + (c & 1) * GSTAGE_B;
        asm volatile("cp.async.wait_group 0;" ::: "memory");
        __syncthreads();   // chunk c ready; reads of other stage (iter c-1) retired
        if (c + 1 < NCH) { // other stage is free now; load overlaps compute below
            load_chunk(sb + ((c + 1) & 1) * GSTAGE_B, A, B, m0, n0, (c + 1) * 64, tid);
            asm volatile("cp.async.commit_group;" ::: "memory");
        }

        #pragma unroll
        for (int s = 0; s < 4; ++s) {          // 4 k-steps of 16 per chunk
            uint32_t ah[4][4], bh[4][2];
            #pragma unroll
            for (int im = 0; im < 4; ++im) {
                int row = mw + im * 16 + ((mid & 1) << 3) + lrow;
                int kc  = 2 * s + (mid >> 1);
                uint32_t addr = sstage + row * 128 + ((kc ^ (row & 7)) * 16);
                ldsm4(ah[im][0], ah[im][1], ah[im][2], ah[im][3], addr);
            }
            #pragma unroll
            for (int jp = 0; jp < 2; ++jp) {
                int row = nw + jp * 16 + ((mid >> 1) << 3) + lrow;
                int kc  = 2 * s + (mid & 1);
                uint32_t addr = sstage + ATILE_B + row * 128 + ((kc ^ (row & 7)) * 16);
                ldsm4(bh[2*jp][0], bh[2*jp][1], bh[2*jp+1][0], bh[2*jp+1][1], addr);
            }
            #pragma unroll
            for (int im = 0; im < 4; ++im)
                #pragma unroll
                for (int jn = 0; jn < 4; ++jn)
                    mma16816(acc[im][jn], ah[im], bh[jn]);
        }
    }

    const int g = lane >> 2, t = lane & 3;
    const float sc = (mode == 0) ? 0.125f : 1.0f;

    #pragma unroll
    for (int im = 0; im < 4; ++im) {
        #pragma unroll
        for (int jn = 0; jn < 4; ++jn) {
            int r0 = m0 + mw + im * 16 + g;
            int cc = n0 + nw + jn * 8 + 2 * t;
            float2 b2v = *reinterpret_cast<const float2*>(bias + cc);
            float v00 = (acc[im][jn][0] + b2v.x) * sc, v01 = (acc[im][jn][1] + b2v.y) * sc;
            float v10 = (acc[im][jn][2] + b2v.x) * sc, v11 = (acc[im][jn][3] + b2v.y) * sc;
            if (mode < 3) {
                int h = cc >> 6, d = cc & 63;
                __half* dst = (mode == 0) ? g_q1 : (mode == 1) ? g_k1 : g_v1;
                #pragma unroll
                for (int rr = 0; rr < 2; ++rr) {
                    int r = r0 + rr * 8;
                    float e0 = rr ? v10 : v00, e1 = rr ? v11 : v01;
                    int b = r >> 11, srow = r & (SEQ - 1);
                    size_t idx = (((size_t)(b * NHEAD + h)) * SEQ + srow) * DKH + d;
                    *reinterpret_cast<uint32_t*>(dst + idx) = packh2(e0, e1);
                }
            } else {
                *reinterpret_cast<float2*>(outp + (size_t)r0 * D_MODEL + cc) = make_float2(v00, v01);
                *reinterpret_cast<float2*>(outp + (size_t)(r0+8) * D_MODEL + cc) = make_float2(v10, v11);
            }
        }
    }
}

// ============================================================================
// Flash attention, fp16 mma.sync — fully single-pass (unchanged from R13).
// __launch_bounds__(256, 2): 128 regs -> 2 CTAs/SM.
// smem: Q 16K, 2 stages x (K 8K, V 8K) = 48KB.
// ============================================================================
#define AT_STAGE 16384
#define AT_SMEM (16384 + 2 * AT_STAGE)   // 49152

__device__ __forceinline__ void load_kv(uint32_t sstage, size_t hoff, int kt, int tid)
{
    const __half* srcs[2] = { g_k1 + hoff, g_v1 + hoff };
    #pragma unroll
    for (int tI = 0; tI < 2; ++tI)
        #pragma unroll
        for (int i = 0; i < 2; ++i) {
            int idx = tid + i * 256;
            int row = idx >> 3, c = idx & 7;
            const void* gsrc = srcs[tI] + (size_t)(kt * 64 + row) * DKH + c * 8;
            uint32_t d = sstage + tI * 8192 + row * 128 + ((c ^ (row & 7)) * 16);
            asm volatile("cp.async.cg.shared.global [%0], [%1], 16;" :: "r"(d), "l"(gsrc));
        }
}

__global__ __launch_bounds__(256, 2)
void flash_mma_kernel()
{
    extern __shared__ __align__(128) char smem[];
    const uint32_t sb = smem_u32(smem);
    const uint32_t sQ = sb, sKV = sb + 16384;

    const int tid = threadIdx.x, wid = tid >> 5, lane = tid & 31;
    const int mid = lane >> 3, lrow = lane & 7;
    const int g = lane >> 2, t = lane & 3;
    const int bh = blockIdx.x;
    const int qt = (int)(gridDim.y - 1 - blockIdx.y);   // heavy tiles first
    const int qbase = qt * 128;
    const size_t hoff = (size_t)bh * SEQ * DKH;
    const int nkt = 2 * qt + 2;

    {
        #pragma unroll
        for (int i = 0; i < 4; ++i) {
            int idx = tid + i * 256;
            int row = idx >> 3, c = idx & 7;
            const void* gsrc = g_q1 + hoff + (size_t)(qbase + row) * DKH + c * 8;
            uint32_t d = sQ + row * 128 + ((c ^ (row & 7)) * 16);
            asm volatile("cp.async.cg.shared.global [%0], [%1], 16;" :: "r"(d), "l"(gsrc));
        }
    }
    load_kv(sKV, hoff, 0, tid);
    asm volatile("cp.async.commit_group;" ::: "memory");
    load_kv(sKV + AT_STAGE, hoff, 1, tid);
    asm volatile("cp.async.commit_group;" ::: "memory");

    float oacc[8][4];
    #pragma unroll
    for (int jn = 0; jn < 8; ++jn)
        #pragma unroll
        for (int r = 0; r < 4; ++r) oacc[jn][r] = 0.f;
    float mrow[2] = {-INFINITY, -INFINITY};
    float lsum[2] = {0.f, 0.f};
    uint32_t qh[4][4];

    for (int kt = 0; kt < nkt; ++kt) {
        if (kt + 1 < nkt) asm volatile("cp.async.wait_group 1;" ::: "memory");
        else              asm volatile("cp.async.wait_group 0;" ::: "memory");
        __syncthreads();

        if (kt == 0) {
            #pragma unroll
            for (int s = 0; s < 4; ++s) {
                int row = wid * 16 + ((mid & 1) << 3) + lrow;
                int kc = 2 * s + (mid >> 1);
                uint32_t a = sQ + row * 128 + ((kc ^ (row & 7)) * 16);
                ldsm4(qh[s][0], qh[s][1], qh[s][2], qh[s][3], a);
            }
        }

        const uint32_t sK = sKV + (kt & 1) * AT_STAGE;
        const uint32_t sV = sK + 8192;

        float sacc[8][4];
        #pragma unroll
        for (int jn = 0; jn < 8; ++jn)
            #pragma unroll
            for (int r = 0; r < 4; ++r) sacc[jn][r] = 0.f;

        #pragma unroll
        for (int s = 0; s < 4; ++s) {
            uint32_t kb[8][2];
            #pragma unroll
            for (int jp = 0; jp < 4; ++jp) {
                int row = jp * 16 + ((mid >> 1) << 3) + lrow;
                int kc = 2 * s + (mid & 1);
                uint32_t a = sK + row * 128 + ((kc ^ (row & 7)) * 16);
                ldsm4(kb[2*jp][0], kb[2*jp][1], kb[2*jp+1][0], kb[2*jp+1][1], a);
            }
            #pragma unroll
            for (int jn = 0; jn < 8; ++jn) mma16816(sacc[jn], qh[s], kb[jn]);
        }

        if (kt >= 2 * qt) {
            int q0 = qbase + wid * 16 + g;
            #pragma unroll
            for (int jn = 0; jn < 8; ++jn) {
                int j0 = kt * 64 + jn * 8 + 2 * t;
                if (j0     > q0)     sacc[jn][0] = -INFINITY;
                if (j0 + 1 > q0)     sacc[jn][1] = -INFINITY;
                if (j0     > q0 + 8) sacc[jn][2] = -INFINITY;
                if (j0 + 1 > q0 + 8) sacc[jn][3] = -INFINITY;
            }
        }

        #pragma unroll
        for (int hf = 0; hf < 2; ++hf) {
            float mx = -INFINITY;
            #pragma unroll
            for (int jn = 0; jn < 8; ++jn)
                mx = fmaxf(mx, fmaxf(sacc[jn][2*hf], sacc[jn][2*hf+1]));
            mx = fmaxf(mx, __shfl_xor_sync(0xffffffffu, mx, 1));
            mx = fmaxf(mx, __shfl_xor_sync(0xffffffffu, mx, 2));
            float mn = fmaxf(mrow[hf], mx);
            float al = __expf(mrow[hf] - mn);
            mrow[hf] = mn;
            float sum = 0.f;
            #pragma unroll
            for (int jn = 0; jn < 8; ++jn) {
                float p0 = __expf(sacc[jn][2*hf]   - mn);
                float p1 = __expf(sacc[jn][2*hf+1] - mn);
                sacc[jn][2*hf] = p0; sacc[jn][2*hf+1] = p1;
                sum += p0 + p1;
            }
            sum += __shfl_xor_sync(0xffffffffu, sum, 1);
            sum += __shfl_xor_sync(0xffffffffu, sum, 2);
            lsum[hf] = lsum[hf] * al + sum;
            #pragma unroll
            for (int jn = 0; jn < 8; ++jn) { oacc[jn][2*hf] *= al; oacc[jn][2*hf+1] *= al; }
        }

        #pragma unroll
        for (int s = 0; s < 4; ++s) {
            uint32_t ph[4];
            #pragma unroll
            for (int r = 0; r < 4; ++r) {
                int tile = 2 * s + (r >> 1);
                int c0 = (r & 1) * 2;
                ph[r] = packh2(sacc[tile][c0], sacc[tile][c0 + 1]);
            }
            uint32_t vb[8][2];
            #pragma unroll
            for (int jp = 0; jp < 4; ++jp) {
                int row = 16 * s + ((mid & 1) << 3) + lrow;
                int c = 2 * jp + (mid >> 1);
                uint32_t a = sV + row * 128 + ((c ^ (row & 7)) * 16);
                ldsm4t(vb[2*jp][0], vb[2*jp][1], vb[2*jp+1][0], vb[2*jp+1][1], a);
            }
            #pragma unroll
            for (int jn = 0; jn < 8; ++jn) mma16816(oacc[jn], ph, vb[jn]);
        }

        __syncthreads();
        if (kt + 2 < nkt) {
            load_kv(sKV + (kt & 1) * AT_STAGE, hoff, kt + 2, tid);
            asm volatile("cp.async.commit_group;" ::: "memory");
        }
    }

    const int b = bh >> 4, h = bh & 15;
    #pragma unroll
    for (int hf = 0; hf < 2; ++hf) {
        float inv = 1.0f / lsum[hf];
        int row = qbase + wid * 16 + g + 8 * hf;
        size_t base = ((size_t)(b * SEQ + row)) * D_MODEL + h * 64;
        #pragma unroll
        for (int jn = 0; jn < 8; ++jn) {
            *reinterpret_cast<uint32_t*>(g_a1 + base + jn * 8 + 2 * t) =
                packh2(oacc[jn][2*hf] * inv, oacc[jn][2*hf+1] * inv);
        }
    }
}

// ============================================================================
extern "C" void kernel_launch(void* const* d_in, const int* in_sizes, int n_in,
                              void* d_out, int out_size)
{
    const float* x  = (const float*)d_in[0];
    const float* Wq = (const float*)d_in[1];
    const float* bq = (const float*)d_in[2];
    const float* Wk = (const float*)d_in[3];
    const float* bk = (const float*)d_in[4];
    const float* Wv = (const float*)d_in[5];
    const float* bv = (const float*)d_in[6];
    const float* Wo = (const float*)d_in[7];
    const float* bo = (const float*)d_in[8];
    float* out = (float*)d_out;

    const int nx4 = M_TOT * D_MODEL / 4;
    const int nw4 = D_MODEL * D_MODEL / 4;

    conv_x_kernel<<<nx4 / 256, 256>>>(x, nx4);
    conv_w4_kernel<<<dim3(nw4 / 256, 4), 256>>>(Wq, Wk, Wv, Wo, nw4);

    cudaFuncSetAttribute(gemm_mma_kernel,
                         cudaFuncAttributeMaxDynamicSharedMemorySize, GEMM_SMEM);

    // fused QKV: blockIdx.z = mode (0=Q, 1=K, 2=V)
    gemm_mma_kernel<<<dim3(D_MODEL / 128, M_TOT / 256, 3), 512, GEMM_SMEM>>>(
        0, bq, bk, bv, nullptr);

    cudaFuncSetAttribute(flash_mma_kernel,
                         cudaFuncAttributeMaxDynamicSharedMemorySize, AT_SMEM);
    flash_mma_kernel<<<dim3(BH, SEQ / 128), 256, AT_SMEM>>>();

    gemm_mma_kernel<<<dim3(D_MODEL / 128, M_TOT / 256, 1), 512, GEMM_SMEM>>>(
        3, bo, bo, bo, out);
}

// round 15
// speedup vs baseline: 1.0208x; 1.0208x over previous
#include <cuda_runtime.h>
#include <cuda_fp16.h>
#include <math.h>
#include <stdint.h>

#define D_MODEL 1024
#define NHEAD   16
#define DKH     64
#define BATCH   4
#define SEQ     2048
#define M_TOT   (BATCH*SEQ)     // 8192
#define BH      (BATCH*NHEAD)   // 64

// ---- scratch (__device__ globals: allocation-free rule) ----
__device__ __half g_x1[(size_t)M_TOT*D_MODEL];       // x single fp16
__device__ __half g_a1[(size_t)M_TOT*D_MODEL];       // attn out single fp16
__device__ __half g_wh[4][(size_t)D_MODEL*D_MODEL];  // weights single fp16
// q (pre-scaled log2e/8), k, v — all single fp16 [B,H,S,dk]
__device__ __half g_q1[(size_t)BH*SEQ*DKH];
__device__ __half g_k1[(size_t)BH*SEQ*DKH];
__device__ __half g_v1[(size_t)BH*SEQ*DKH];

typedef unsigned long long ull;

__device__ __forceinline__ uint32_t smem_u32(const void* p) {
    uint32_t a;
    asm("{ .reg .u64 t; cvta.to.shared.u64 t, %1; cvt.u32.u64 %0, t; }" : "=r"(a) : "l"(p));
    return a;
}
__device__ __forceinline__ void ldsm4(uint32_t& r0, uint32_t& r1, uint32_t& r2, uint32_t& r3,
                                      uint32_t addr) {
    asm volatile("ldmatrix.sync.aligned.m8n8.x4.shared.b16 {%0,%1,%2,%3}, [%4];"
                 : "=r"(r0), "=r"(r1), "=r"(r2), "=r"(r3) : "r"(addr));
}
__device__ __forceinline__ void ldsm4t(uint32_t& r0, uint32_t& r1, uint32_t& r2, uint32_t& r3,
                                       uint32_t addr) {
    asm volatile("ldmatrix.sync.aligned.m8n8.x4.trans.shared.b16 {%0,%1,%2,%3}, [%4];"
                 : "=r"(r0), "=r"(r1), "=r"(r2), "=r"(r3) : "r"(addr));
}
__device__ __forceinline__ void mma16816(float* c, const uint32_t* a, const uint32_t* b) {
    asm volatile(
        "mma.sync.aligned.m16n8k16.row.col.f32.f16.f16.f32 "
        "{%0,%1,%2,%3}, {%4,%5,%6,%7}, {%8,%9}, {%0,%1,%2,%3};"
        : "+f"(c[0]), "+f"(c[1]), "+f"(c[2]), "+f"(c[3])
        : "r"(a[0]), "r"(a[1]), "r"(a[2]), "r"(a[3]), "r"(b[0]), "r"(b[1]));
}
// pack two f32 -> fp16x2 (e0 low)
__device__ __forceinline__ uint32_t packh2(float e0, float e1) {
    __half2 hh = __floats2half2_rn(e0, e1);
    return *reinterpret_cast<uint32_t*>(&hh);
}
// bare hardware exp2 (scores are pre-scaled into log2 domain)
__device__ __forceinline__ float ex2f(float x) {
    float r; asm("ex2.approx.f32 %0, %1;" : "=f"(r) : "f"(x)); return r;
}

// ============================================================================
// conversions: x -> g_x1;  4 weights -> g_wh (single launch, blockIdx.y)
// ============================================================================
__global__ void conv_x_kernel(const float* __restrict__ in, int n4)
{
    int i = blockIdx.x * blockDim.x + threadIdx.x;
    if (i >= n4) return;
    float4 v = reinterpret_cast<const float4*>(in)[i];
    __half h[4];
    h[0] = __float2half_rn(v.x); h[1] = __float2half_rn(v.y);
    h[2] = __float2half_rn(v.z); h[3] = __float2half_rn(v.w);
    reinterpret_cast<ull*>(g_x1)[i] = *reinterpret_cast<ull*>(h);
}

__global__ void conv_w4_kernel(const float* __restrict__ W0, const float* __restrict__ W1,
                               const float* __restrict__ W2, const float* __restrict__ W3,
                               int n4)
{
    int which = blockIdx.y;
    const float* src = (which == 0) ? W0 : (which == 1) ? W1 : (which == 2) ? W2 : W3;
    int i = blockIdx.x * blockDim.x + threadIdx.x;
    if (i >= n4) return;
    float4 v = reinterpret_cast<const float4*>(src)[i];
    __half h[4];
    h[0] = __float2half_rn(v.x); h[1] = __float2half_rn(v.y);
    h[2] = __float2half_rn(v.z); h[3] = __float2half_rn(v.w);
    reinterpret_cast<ull*>(g_wh[which])[i] = *reinterpret_cast<ull*>(h);
}

// ============================================================================
// mma.sync fp16 GEMM — single-pass, CTA 128x128, K-chunk 64, 3-stage ring.
// (reverted to the validated R13 configuration)
// Epilogues: 0 q*(log2e/8), 1 K, 2 V (fp16); 3 fp32+bias.
// ============================================================================
#define GTILE_B 16384                // 128 rows x 128B (64 halves)
#define GSTAGE_B (2 * GTILE_B)       // A, B
#define GEMM_SMEM (3 * GSTAGE_B)     // 98304

__device__ __forceinline__ void load_chunk(
    uint32_t sstage, const __half* A, const __half* B,
    int m0, int n0, int k0, int tid)
{
    const __half* srcs[2] = {A, B};
    const int bases[2] = {m0, n0};
    #pragma unroll
    for (int t = 0; t < 2; ++t) {
        #pragma unroll
        for (int i = 0; i < 2; ++i) {
            int idx = tid + i * 512;               // 1024 x 16B per tile
            int row = idx >> 3, c = idx & 7;
            const void* g = srcs[t] + (size_t)(bases[t] + row) * D_MODEL + k0 + c * 8;
            uint32_t s = sstage + t * GTILE_B + row * 128 + ((c ^ (row & 7)) * 16);
            asm volatile("cp.async.cg.shared.global [%0], [%1], 16;" :: "r"(s), "l"(g));
        }
    }
}

__global__ __launch_bounds__(512, 1)
void gemm_mma_kernel(int mode_base, const float* __restrict__ b0,
                     const float* __restrict__ b1, const float* __restrict__ b2,
                     float* __restrict__ outp)
{
    extern __shared__ __align__(128) char smem[];
    const uint32_t sb = smem_u32(smem);

    const int mode = (mode_base == 3) ? 3 : (int)blockIdx.z;
    const float* bias = (mode == 1) ? b1 : (mode == 2) ? b2 : b0;
    const __half* A = (mode == 3) ? g_a1 : g_x1;
    const __half* B = g_wh[mode];

    const int tid = threadIdx.x, wid = tid >> 5, lane = tid & 31;
    const int m0 = blockIdx.y * 128, n0 = blockIdx.x * 128;
    const int mw = (wid & 3) * 32, nw = (wid >> 2) * 32;   // 4x4 warp grid
    const int mid = lane >> 3, lrow = lane & 7;

    float acc[2][4][4];
    #pragma unroll
    for (int im = 0; im < 2; ++im)
        #pragma unroll
        for (int jn = 0; jn < 4; ++jn)
            #pragma unroll
            for (int r = 0; r < 4; ++r) acc[im][jn][r] = 0.f;

    load_chunk(sb, A, B, m0, n0, 0, tid);
    asm volatile("cp.async.commit_group;" ::: "memory");
    load_chunk(sb + GSTAGE_B, A, B, m0, n0, 64, tid);
    asm volatile("cp.async.commit_group;" ::: "memory");

    const int NCH = D_MODEL / 64;   // 16
    for (int c = 0; c < NCH; ++c) {
        const uint32_t sstage = sb + (c % 3) * GSTAGE_B;
        if (c + 1 < NCH) asm volatile("cp.async.wait_group 1;" ::: "memory");
        else             asm volatile("cp.async.wait_group 0;" ::: "memory");
        __syncthreads();

        #pragma unroll
        for (int s = 0; s < 4; ++s) {          // 4 k-steps of 16 per chunk
            uint32_t ah[2][4], bh[4][2];
            #pragma unroll
            for (int im = 0; im < 2; ++im) {
                int row = mw + im * 16 + ((mid & 1) << 3) + lrow;
                int kc  = 2 * s + (mid >> 1);
                uint32_t addr = sstage + row * 128 + ((kc ^ (row & 7)) * 16);
                ldsm4(ah[im][0], ah[im][1], ah[im][2], ah[im][3], addr);
            }
            #pragma unroll
            for (int jp = 0; jp < 2; ++jp) {
                int row = nw + jp * 16 + ((mid >> 1) << 3) + lrow;
                int kc  = 2 * s + (mid & 1);
                uint32_t addr = sstage + GTILE_B + row * 128 + ((kc ^ (row & 7)) * 16);
                ldsm4(bh[2*jp][0], bh[2*jp][1], bh[2*jp+1][0], bh[2*jp+1][1], addr);
            }
            #pragma unroll
            for (int im = 0; im < 2; ++im)
                #pragma unroll
                for (int jn = 0; jn < 4; ++jn)
                    mma16816(acc[im][jn], ah[im], bh[jn]);
        }
        if (c + 2 < NCH) {
            load_chunk(sb + ((c + 2) % 3) * GSTAGE_B, A, B, m0, n0, (c + 2) * 64, tid);
            asm volatile("cp.async.commit_group;" ::: "memory");
        }
    }

    const int g = lane >> 2, t = lane & 3;
    // Q pre-scale includes log2(e): softmax runs in base-2 domain downstream.
    const float sc = (mode == 0) ? 0.125f * 1.4426950408889634f : 1.0f;

    #pragma unroll
    for (int im = 0; im < 2; ++im) {
        #pragma unroll
        for (int jn = 0; jn < 4; ++jn) {
            int r0 = m0 + mw + im * 16 + g;
            int cc = n0 + nw + jn * 8 + 2 * t;
            float2 b2v = *reinterpret_cast<const float2*>(bias + cc);
            float v00 = (acc[im][jn][0] + b2v.x) * sc, v01 = (acc[im][jn][1] + b2v.y) * sc;
            float v10 = (acc[im][jn][2] + b2v.x) * sc, v11 = (acc[im][jn][3] + b2v.y) * sc;
            if (mode < 3) {
                int h = cc >> 6, d = cc & 63;
                __half* dst = (mode == 0) ? g_q1 : (mode == 1) ? g_k1 : g_v1;
                #pragma unroll
                for (int rr = 0; rr < 2; ++rr) {
                    int r = r0 + rr * 8;
                    float e0 = rr ? v10 : v00, e1 = rr ? v11 : v01;
                    int b = r >> 11, srow = r & (SEQ - 1);
                    size_t idx = (((size_t)(b * NHEAD + h)) * SEQ + srow) * DKH + d;
                    *reinterpret_cast<uint32_t*>(dst + idx) = packh2(e0, e1);
                }
            } else {
                *reinterpret_cast<float2*>(outp + (size_t)r0 * D_MODEL + cc) = make_float2(v00, v01);
                *reinterpret_cast<float2*>(outp + (size_t)(r0+8) * D_MODEL + cc) = make_float2(v10, v11);
            }
        }
    }
}

// ============================================================================
// Flash attention, fp16 mma.sync — single-pass, base-2 online softmax.
// Scores arrive pre-scaled by log2e/8, so exp == bare ex2.approx.
// __launch_bounds__(256, 2): 128 regs -> 2 CTAs/SM.
// smem: Q 16K, 2 stages x (K 8K, V 8K) = 48KB.
// ============================================================================
#define AT_STAGE 16384
#define AT_SMEM (16384 + 2 * AT_STAGE)   // 49152

__device__ __forceinline__ void load_kv(uint32_t sstage, size_t hoff, int kt, int tid)
{
    const __half* srcs[2] = { g_k1 + hoff, g_v1 + hoff };
    #pragma unroll
    for (int tI = 0; tI < 2; ++tI)
        #pragma unroll
        for (int i = 0; i < 2; ++i) {
            int idx = tid + i * 256;
            int row = idx >> 3, c = idx & 7;
            const void* gsrc = srcs[tI] + (size_t)(kt * 64 + row) * DKH + c * 8;
            uint32_t d = sstage + tI * 8192 + row * 128 + ((c ^ (row & 7)) * 16);
            asm volatile("cp.async.cg.shared.global [%0], [%1], 16;" :: "r"(d), "l"(gsrc));
        }
}

__global__ __launch_bounds__(256, 2)
void flash_mma_kernel()
{
    extern __shared__ __align__(128) char smem[];
    const uint32_t sb = smem_u32(smem);
    const uint32_t sQ = sb, sKV = sb + 16384;

    const int tid = threadIdx.x, wid = tid >> 5, lane = tid & 31;
    const int mid = lane >> 3, lrow = lane & 7;
    const int g = lane >> 2, t = lane & 3;
    const int bh = blockIdx.x;
    const int qt = (int)(gridDim.y - 1 - blockIdx.y);   // heavy tiles first
    const int qbase = qt * 128;
    const size_t hoff = (size_t)bh * SEQ * DKH;
    const int nkt = 2 * qt + 2;

    {
        #pragma unroll
        for (int i = 0; i < 4; ++i) {
            int idx = tid + i * 256;
            int row = idx >> 3, c = idx & 7;
            const void* gsrc = g_q1 + hoff + (size_t)(qbase + row) * DKH + c * 8;
            uint32_t d = sQ + row * 128 + ((c ^ (row & 7)) * 16);
            asm volatile("cp.async.cg.shared.global [%0], [%1], 16;" :: "r"(d), "l"(gsrc));
        }
    }
    load_kv(sKV, hoff, 0, tid);
    asm volatile("cp.async.commit_group;" ::: "memory");
    load_kv(sKV + AT_STAGE, hoff, 1, tid);
    asm volatile("cp.async.commit_group;" ::: "memory");

    float oacc[8][4];
    #pragma unroll
    for (int jn = 0; jn < 8; ++jn)
        #pragma unroll
        for (int r = 0; r < 4; ++r) oacc[jn][r] = 0.f;
    float mrow[2] = {-INFINITY, -INFINITY};
    float lsum[2] = {0.f, 0.f};
    uint32_t qh[4][4];

    for (int kt = 0; kt < nkt; ++kt) {
        if (kt + 1 < nkt) asm volatile("cp.async.wait_group 1;" ::: "memory");
        else              asm volatile("cp.async.wait_group 0;" ::: "memory");
        __syncthreads();

        if (kt == 0) {
            #pragma unroll
            for (int s = 0; s < 4; ++s) {
                int row = wid * 16 + ((mid & 1) << 3) + lrow;
                int kc = 2 * s + (mid >> 1);
                uint32_t a = sQ + row * 128 + ((kc ^ (row & 7)) * 16);
                ldsm4(qh[s][0], qh[s][1], qh[s][2], qh[s][3], a);
            }
        }

        const uint32_t sK = sKV + (kt & 1) * AT_STAGE;
        const uint32_t sV = sK + 8192;

        // ---- S = q·K (single pass; result already in log2 units) ----
        float sacc[8][4];
        #pragma unroll
        for (int jn = 0; jn < 8; ++jn)
            #pragma unroll
            for (int r = 0; r < 4; ++r) sacc[jn][r] = 0.f;

        #pragma unroll
        for (int s = 0; s < 4; ++s) {
            uint32_t kb[8][2];
            #pragma unroll
            for (int jp = 0; jp < 4; ++jp) {
                int row = jp * 16 + ((mid >> 1) << 3) + lrow;
                int kc = 2 * s + (mid & 1);
                uint32_t a = sK + row * 128 + ((kc ^ (row & 7)) * 16);
                ldsm4(kb[2*jp][0], kb[2*jp][1], kb[2*jp+1][0], kb[2*jp+1][1], a);
            }
            #pragma unroll
            for (int jn = 0; jn < 8; ++jn) mma16816(sacc[jn], qh[s], kb[jn]);
        }

        if (kt >= 2 * qt) {
            int q0 = qbase + wid * 16 + g;
            #pragma unroll
            for (int jn = 0; jn < 8; ++jn) {
                int j0 = kt * 64 + jn * 8 + 2 * t;
                if (j0     > q0)     sacc[jn][0] = -INFINITY;
                if (j0 + 1 > q0)     sacc[jn][1] = -INFINITY;
                if (j0     > q0 + 8) sacc[jn][2] = -INFINITY;
                if (j0 + 1 > q0 + 8) sacc[jn][3] = -INFINITY;
            }
        }

        // ---- online softmax, base-2 (exp == bare ex2.approx) ----
        #pragma unroll
        for (int hf = 0; hf < 2; ++hf) {
            float mx = -INFINITY;
            #pragma unroll
            for (int jn = 0; jn < 8; ++jn)
                mx = fmaxf(mx, fmaxf(sacc[jn][2*hf], sacc[jn][2*hf+1]));
            mx = fmaxf(mx, __shfl_xor_sync(0xffffffffu, mx, 1));
            mx = fmaxf(mx, __shfl_xor_sync(0xffffffffu, mx, 2));
            float mn = fmaxf(mrow[hf], mx);
            float al = ex2f(mrow[hf] - mn);      // -inf -> 0 on first tile
            mrow[hf] = mn;
            float sum = 0.f;
            #pragma unroll
            for (int jn = 0; jn < 8; ++jn) {
                float p0 = ex2f(sacc[jn][2*hf]   - mn);
                float p1 = ex2f(sacc[jn][2*hf+1] - mn);
                sacc[jn][2*hf] = p0; sacc[jn][2*hf+1] = p1;
                sum += p0 + p1;
            }
            sum += __shfl_xor_sync(0xffffffffu, sum, 1);
            sum += __shfl_xor_sync(0xffffffffu, sum, 2);
            lsum[hf] = lsum[hf] * al + sum;
            #pragma unroll
            for (int jn = 0; jn < 8; ++jn) { oacc[jn][2*hf] *= al; oacc[jn][2*hf+1] *= al; }
        }

        // ---- O += P V (single pass; P rounded to fp16 in registers) ----
        #pragma unroll
        for (int s = 0; s < 4; ++s) {
            uint32_t ph[4];
            #pragma unroll
            for (int r = 0; r < 4; ++r) {
                int tile = 2 * s + (r >> 1);
                int c0 = (r & 1) * 2;
                ph[r] = packh2(sacc[tile][c0], sacc[tile][c0 + 1]);
            }
            uint32_t vb[8][2];
            #pragma unroll
            for (int jp = 0; jp < 4; ++jp) {
                int row = 16 * s + ((mid & 1) << 3) + lrow;
                int c = 2 * jp + (mid >> 1);
                uint32_t a = sV + row * 128 + ((c ^ (row & 7)) * 16);
                ldsm4t(vb[2*jp][0], vb[2*jp][1], vb[2*jp+1][0], vb[2*jp+1][1], a);
            }
            #pragma unroll
            for (int jn = 0; jn < 8; ++jn) mma16816(oacc[jn], ph, vb[jn]);
        }

        __syncthreads();
        if (kt + 2 < nkt) {
            load_kv(sKV + (kt & 1) * AT_STAGE, hoff, kt + 2, tid);
            asm volatile("cp.async.commit_group;" ::: "memory");
        }
    }

    // ---- normalize + write single fp16 into [B,S,H*dk] (g_a1) ----
    const int b = bh >> 4, h = bh & 15;
    #pragma unroll
    for (int hf = 0; hf < 2; ++hf) {
        float inv = 1.0f / lsum[hf];
        int row = qbase + wid * 16 + g + 8 * hf;
        size_t base = ((size_t)(b * SEQ + row)) * D_MODEL + h * 64;
        #pragma unroll
        for (int jn = 0; jn < 8; ++jn) {
            *reinterpret_cast<uint32_t*>(g_a1 + base + jn * 8 + 2 * t) =
                packh2(oacc[jn][2*hf] * inv, oacc[jn][2*hf+1] * inv);
        }
    }
}

// ============================================================================
extern "C" void kernel_launch(void* const* d_in, const int* in_sizes, int n_in,
                              void* d_out, int out_size)
{
    const float* x  = (const float*)d_in[0];
    const float* Wq = (const float*)d_in[1];
    const float* bq = (const float*)d_in[2];
    const float* Wk = (const float*)d_in[3];
    const float* bk = (const float*)d_in[4];
    const float* Wv = (const float*)d_in[5];
    const float* bv = (const float*)d_in[6];
    const float* Wo = (const float*)d_in[7];
    const float* bo = (const float*)d_in[8];
    float* out = (float*)d_out;

    const int nx4 = M_TOT * D_MODEL / 4;
    const int nw4 = D_MODEL * D_MODEL / 4;

    conv_x_kernel<<<nx4 / 256, 256>>>(x, nx4);
    conv_w4_kernel<<<dim3(nw4 / 256, 4), 256>>>(Wq, Wk, Wv, Wo, nw4);

    cudaFuncSetAttribute(gemm_mma_kernel,
                         cudaFuncAttributeMaxDynamicSharedMemorySize, GEMM_SMEM);

    // fused QKV: blockIdx.z = mode (0=Q, 1=K, 2=V)
    gemm_mma_kernel<<<dim3(D_MODEL / 128, M_TOT / 128, 3), 512, GEMM_SMEM>>>(
        0, bq, bk, bv, nullptr);

    cudaFuncSetAttribute(flash_mma_kernel,
                         cudaFuncAttributeMaxDynamicSharedMemorySize, AT_SMEM);
    flash_mma_kernel<<<dim3(BH, SEQ / 128), 256, AT_SMEM>>>();

    gemm_mma_kernel<<<dim3(D_MODEL / 128, M_TOT / 128, 1), 512, GEMM_SMEM>>>(
        3, bo, bo, bo, out);
}